// round 14
// baseline (speedup 1.0000x reference)
#include <cuda_runtime.h>
#include <cstdint>

#define N_NODES 100000
#define N_EDGES 1600000
#define CH      128
#define EDIM    16
#define NB      391      // ceil(N_NODES/256)

// ---------------- scratch (static device globals: no allocation) ----------------
__device__ float g_nodeproj[(size_t)N_NODES * CH];
__device__ float g_summed [(size_t)N_NODES * CH];
__device__ float g_h      [(size_t)N_NODES * CH];
__device__ float g_inv    [N_NODES];
__device__ int   g_cnt    [N_NODES];
__device__ int   g_off    [N_NODES];
__device__ int   g_cursor [N_NODES];
__device__ int   g_part   [512];
__device__ int   g_src_sorted[N_EDGES];
__device__ int   g_dst_sorted[N_EDGES];
__device__ float g_ea_sorted[(size_t)N_EDGES * EDIM];
__device__ int   g_is64;

// ---------------- packed f32x2 helpers (sm_103a) ----------------
static __device__ __forceinline__ unsigned long long pack2(float x, float y) {
    unsigned long long r;
    asm("mov.b64 %0, {%1, %2};" : "=l"(r) : "f"(x), "f"(y));
    return r;
}
static __device__ __forceinline__ void unpack2(unsigned long long v, float &x, float &y) {
    asm("mov.b64 {%0, %1}, %2;" : "=f"(x), "=f"(y) : "l"(v));
}
static __device__ __forceinline__ void ffma2(unsigned long long &d,
                                             unsigned long long a,
                                             unsigned long long b) {
    asm("fma.rn.f32x2 %0, %1, %2, %0;" : "+l"(d) : "l"(a), "l"(b));
}

// ---------------- init: zero counts + dtype sniff (int32 vs int64) -------------
__global__ void init_kernel(const unsigned* __restrict__ p) {
    int i = blockIdx.x * 256 + threadIdx.x;
    if (i < N_NODES) g_cnt[i] = 0;
    if (blockIdx.x == 0) {
        __shared__ int nz;
        if (threadIdx.x == 0) nz = 0;
        __syncthreads();
        if (p[threadIdx.x * 2 + 1] != 0u) atomicAdd(&nz, 1);
        __syncthreads();
        if (threadIdx.x == 0) g_is64 = (nz == 0) ? 1 : 0;
    }
}

static __device__ __forceinline__ int load_eidx(const void* eidx, long long i, int is64) {
    return is64 ? (int)((const long long*)eidx)[i] : ((const int*)eidx)[i];
}

__global__ void count_kernel(const void* __restrict__ eidx) {
    long long t = (long long)blockIdx.x * blockDim.x + threadIdx.x;
    if (t >= N_EDGES) return;
    int dst = load_eidx(eidx, (long long)N_EDGES + t, g_is64);
    atomicAdd(&g_cnt[dst], 1);
}

// ---------------- parallel 3-phase exclusive scan of g_cnt ----------------------
__global__ __launch_bounds__(256) void reduce_kernel() {
    int i = blockIdx.x * 256 + threadIdx.x;
    int x = (i < N_NODES) ? g_cnt[i] : 0;
    __shared__ int ws[8];
    int lane = threadIdx.x & 31, wid = threadIdx.x >> 5;
#pragma unroll
    for (int o = 16; o; o >>= 1) x += __shfl_down_sync(0xffffffffu, x, o);
    if (lane == 0) ws[wid] = x;
    __syncthreads();
    if (wid == 0) {
        int v = (lane < 8) ? ws[lane] : 0;
#pragma unroll
        for (int o = 4; o; o >>= 1) v += __shfl_down_sync(0xffffffffu, v, o);
        if (lane == 0) g_part[blockIdx.x] = v;
    }
}

__global__ __launch_bounds__(512) void scanp_kernel() {
    int tid = threadIdx.x, lane = tid & 31, wid = tid >> 5;
    int v = (tid < NB) ? g_part[tid] : 0;
    int x = v;
#pragma unroll
    for (int o = 1; o < 32; o <<= 1) {
        int y = __shfl_up_sync(0xffffffffu, x, o);
        if (lane >= o) x += y;
    }
    __shared__ int ws[16];
    if (lane == 31) ws[wid] = x;
    __syncthreads();
    if (wid == 0) {
        int t = (lane < 16) ? ws[lane] : 0;
#pragma unroll
        for (int o = 1; o < 16; o <<= 1) {
            int y = __shfl_up_sync(0xffffffffu, t, o);
            if (lane >= o) t += y;
        }
        if (lane < 16) ws[lane] = t;
    }
    __syncthreads();
    int pre = wid ? ws[wid - 1] : 0;
    if (tid < NB) g_part[tid] = pre + x - v;   // exclusive
}

__global__ __launch_bounds__(256) void expand_kernel() {
    int i = blockIdx.x * 256 + threadIdx.x;
    int v = (i < N_NODES) ? g_cnt[i] : 0;
    int lane = threadIdx.x & 31, wid = threadIdx.x >> 5;
    int x = v;
#pragma unroll
    for (int o = 1; o < 32; o <<= 1) {
        int y = __shfl_up_sync(0xffffffffu, x, o);
        if (lane >= o) x += y;
    }
    __shared__ int ws[8];
    if (lane == 31) ws[wid] = x;
    __syncthreads();
    if (wid == 0) {
        int t = (lane < 8) ? ws[lane] : 0;
#pragma unroll
        for (int o = 1; o < 8; o <<= 1) {
            int y = __shfl_up_sync(0xffffffffu, t, o);
            if (lane >= o) t += y;
        }
        if (lane < 8) ws[lane] = t;
    }
    __syncthreads();
    int excl = (wid ? ws[wid - 1] : 0) + x - v + g_part[blockIdx.x];
    if (i < N_NODES) {
        g_off[i] = excl;
        g_cursor[i] = excl;
        g_inv[i] = 1.0f / (float)(v > 1 ? v : 1);
    }
}

// scatter edges into dst-sorted order (src, dst, edge_attr payload)
__global__ void scatter_kernel(const void* __restrict__ eidx,
                               const float* __restrict__ edge_attr) {
    long long t = (long long)blockIdx.x * blockDim.x + threadIdx.x;
    if (t >= N_EDGES) return;
    const int is64 = g_is64;
    int src = load_eidx(eidx, t, is64);
    int dst = load_eidx(eidx, (long long)N_EDGES + t, is64);
    int pos = atomicAdd(&g_cursor[dst], 1);
    g_src_sorted[pos] = src;
    g_dst_sorted[pos] = dst;
    const float4* s = reinterpret_cast<const float4*>(&edge_attr[t * EDIM]);
    float4* d = reinterpret_cast<float4*>(&g_ea_sorted[(size_t)pos * EDIM]);
    d[0] = s[0]; d[1] = s[1]; d[2] = s[2]; d[3] = s[3];
}

__global__ void zero_summed_kernel() {
    size_t i = (size_t)blockIdx.x * 256 + threadIdx.x;
    if (i < (size_t)N_NODES * (CH / 4))
        reinterpret_cast<float4*>(g_summed)[i] = make_float4(0.f, 0.f, 0.f, 0.f);
}

// ---------------- double-buffered tiled GEMM (R9-proven: 256thr, 8x8) -----------
// C[N,128] = [A0 | A1*inv[row]] @ B[KTOT,128] (+epilogue). BM=BN=128, BK=16.
template<int KTOT>
static __device__ __forceinline__ float4 loadA_elem(const float* __restrict__ A0,
                                                    const float* __restrict__ A1,
                                                    const float* __restrict__ inv,
                                                    int grow, int kb, int k4) {
    float4 v = make_float4(0.f, 0.f, 0.f, 0.f);
    if (grow < N_NODES) {
        if (KTOT == 128 || kb < 128) {
            v = *reinterpret_cast<const float4*>(&A0[(size_t)grow * 128 + kb + k4]);
        } else {
            v = *reinterpret_cast<const float4*>(&A1[(size_t)grow * 128 + (kb - 128) + k4]);
            float s = inv[grow];
            v.x *= s; v.y *= s; v.z *= s; v.w *= s;
        }
    }
    return v;
}

static __device__ __forceinline__ void stsA(float* As, int m, int k4, float4 v) {
    As[(k4 + 0) * 128 + m] = v.x;
    As[(k4 + 1) * 128 + m] = v.y;
    As[(k4 + 2) * 128 + m] = v.z;
    As[(k4 + 3) * 128 + m] = v.w;
}

static __device__ __forceinline__ void gemm_compute(const float* __restrict__ As,
                                                    const float* __restrict__ Bs,
                                                    unsigned long long acc[8][4],
                                                    int tx, int ty) {
#pragma unroll
    for (int k = 0; k < 16; k++) {
        float4 a0 = *reinterpret_cast<const float4*>(&As[k * 128 + ty * 8]);
        float4 a1 = *reinterpret_cast<const float4*>(&As[k * 128 + ty * 8 + 4]);
        ulonglong2 bb0 = *reinterpret_cast<const ulonglong2*>(&Bs[k * 128 + tx * 8]);
        ulonglong2 bb1 = *reinterpret_cast<const ulonglong2*>(&Bs[k * 128 + tx * 8 + 4]);
        float av[8] = {a0.x, a0.y, a0.z, a0.w, a1.x, a1.y, a1.z, a1.w};
        unsigned long long bv[4] = {bb0.x, bb0.y, bb1.x, bb1.y};
#pragma unroll
        for (int i = 0; i < 8; i++) {
            unsigned long long a2 = pack2(av[i], av[i]);
#pragma unroll
            for (int j = 0; j < 4; j++) ffma2(acc[i][j], a2, bv[j]);
        }
    }
}

template<int KTOT, bool NORM, bool RELU>
__global__ __launch_bounds__(256)
void gemm_kernel(const float* __restrict__ A0, const float* __restrict__ A1,
                 const float* __restrict__ inv,
                 const float* __restrict__ B,
                 const float* __restrict__ bias1, const float* __restrict__ bias2,
                 float* __restrict__ out)
{
    __shared__ float As[2][16 * 128];
    __shared__ float Bs[2][16 * 128];
    const int tid = threadIdx.x;
    const int tx = tid & 15, ty = tid >> 4;
    const int row0 = blockIdx.x * 128;
    const int mA = tid >> 2, k4 = (tid & 3) << 2;
    const int kB = tid >> 5, n4 = tid & 31;

    unsigned long long acc[8][4];
#pragma unroll
    for (int i = 0; i < 8; i++)
#pragma unroll
        for (int j = 0; j < 4; j++) acc[i][j] = 0ull;

    float4 ra0 = loadA_elem<KTOT>(A0, A1, inv, row0 + mA, 0, k4);
    float4 ra1 = loadA_elem<KTOT>(A0, A1, inv, row0 + mA + 64, 0, k4);
    float4 rb0 = reinterpret_cast<const float4*>(&B[(size_t)kB * 128])[n4];
    float4 rb1 = reinterpret_cast<const float4*>(&B[(size_t)(kB + 8) * 128])[n4];
    stsA(As[0], mA, k4, ra0);
    stsA(As[0], mA + 64, k4, ra1);
    reinterpret_cast<float4*>(&Bs[0][kB * 128])[n4] = rb0;
    reinterpret_cast<float4*>(&Bs[0][(kB + 8) * 128])[n4] = rb1;
    __syncthreads();

    int buf = 0;
    for (int kb = 16; kb < KTOT; kb += 16) {
        ra0 = loadA_elem<KTOT>(A0, A1, inv, row0 + mA, kb, k4);
        ra1 = loadA_elem<KTOT>(A0, A1, inv, row0 + mA + 64, kb, k4);
        rb0 = reinterpret_cast<const float4*>(&B[(size_t)(kb + kB) * 128])[n4];
        rb1 = reinterpret_cast<const float4*>(&B[(size_t)(kb + kB + 8) * 128])[n4];
        gemm_compute(As[buf], Bs[buf], acc, tx, ty);
        stsA(As[buf ^ 1], mA, k4, ra0);
        stsA(As[buf ^ 1], mA + 64, k4, ra1);
        reinterpret_cast<float4*>(&Bs[buf ^ 1][kB * 128])[n4] = rb0;
        reinterpret_cast<float4*>(&Bs[buf ^ 1][(kB + 8) * 128])[n4] = rb1;
        __syncthreads();
        buf ^= 1;
    }
    gemm_compute(As[buf], Bs[buf], acc, tx, ty);

    // epilogue
    float vals[8][8];
#pragma unroll
    for (int i = 0; i < 8; i++)
#pragma unroll
        for (int j = 0; j < 4; j++)
            unpack2(acc[i][j], vals[i][2 * j], vals[i][2 * j + 1]);

#pragma unroll
    for (int j = 0; j < 8; j++) {
        float b = bias1[tx * 8 + j];
#pragma unroll
        for (int i = 0; i < 8; i++) vals[i][j] += b;
    }

    float rn[8];
    if (NORM) {
        __syncthreads();
        float* ss = As[0];
        if (tid < 128) ss[tid] = 0.f;
        __syncthreads();
#pragma unroll
        for (int i = 0; i < 8; i++) {
            float p = 0.f;
#pragma unroll
            for (int j = 0; j < 8; j++) p += vals[i][j] * vals[i][j];
            atomicAdd(&ss[ty * 8 + i], p);
        }
        __syncthreads();
        if (tid < 128) {
            float s = ss[tid];
            Bs[0][tid] = 1.0f / fmaxf(sqrtf(s), 1e-12f);
        }
        __syncthreads();
#pragma unroll
        for (int i = 0; i < 8; i++) rn[i] = Bs[0][ty * 8 + i];
    }

#pragma unroll
    for (int i = 0; i < 8; i++) {
        int grow = row0 + ty * 8 + i;
        if (grow < N_NODES) {
            float o[8];
#pragma unroll
            for (int j = 0; j < 8; j++) {
                float v = vals[i][j];
                if (NORM) v = v * rn[i] + bias2[tx * 8 + j];
                if (RELU) v = fmaxf(v, 0.f);
                o[j] = v;
            }
            float4* dst = reinterpret_cast<float4*>(&out[(size_t)grow * 128 + tx * 8]);
            dst[0] = make_float4(o[0], o[1], o[2], o[3]);
            dst[1] = make_float4(o[4], o[5], o[6], o[7]);
        }
    }
}

// ---------------- edge-parallel message kernel v4 --------------------------------
// 32 edges/warp, W in REGISTERS (shfl broadcast on MIO pipe, no crossbar),
// depth-1 pair prefetch pipeline, per-edge flush via run-end bitmask.
__global__ __launch_bounds__(128)
void edgemsg_kernel(const float* __restrict__ nodeproj,
                    const float* __restrict__ We,   // [16][128] row-major fp32
                    float* __restrict__ summed)
{
    const int lane = threadIdx.x & 31;
    const int warp = threadIdx.x >> 5;

    // lane owns output channels [4*lane, 4*lane+4)
    ulonglong2 w[16];
#pragma unroll
    for (int k = 0; k < 16; k++)
        w[k] = reinterpret_cast<const ulonglong2*>(We)[k * 32 + lane];

    const long long e0 = ((long long)blockIdx.x * 4 + warp) * 32;
    if (e0 >= N_EDGES) return;
    const float4* np4 = reinterpret_cast<const float4*>(nodeproj);

    const int srcs = g_src_sorted[e0 + lane];
    const int dsts = g_dst_sorted[e0 + lane];
    // run-end mask: bit e set iff edge e is the last edge of its dst run in chunk
    const int nxt = __shfl_down_sync(0xffffffffu, dsts, 1);
    const unsigned fmask = __ballot_sync(0xffffffffu, lane == 31 || dsts != nxt);

    // prologue: prefetch pair 0
    int sa = __shfl_sync(0xffffffffu, srcs, 0);
    int sb = __shfl_sync(0xffffffffu, srcs, 1);
    float eav = g_ea_sorted[e0 * EDIM + lane];
    float4 a4 = np4[(size_t)sa * 32 + lane];
    float4 b4 = np4[(size_t)sb * 32 + lane];

    float s0 = 0.f, s1 = 0.f, s2 = 0.f, s3 = 0.f;

#pragma unroll 1
    for (int p = 0; p < 16; p++) {
        // prefetch pair p+1 while computing pair p
        float eav_n = 0.f;
        float4 a4n = make_float4(0.f, 0.f, 0.f, 0.f);
        float4 b4n = a4n;
        if (p < 15) {
            int na = __shfl_sync(0xffffffffu, srcs, 2 * p + 2);
            int nb = __shfl_sync(0xffffffffu, srcs, 2 * p + 3);
            eav_n = g_ea_sorted[(e0 + 2 * p + 2) * EDIM + lane];
            a4n = np4[(size_t)na * 32 + lane];
            b4n = np4[(size_t)nb * 32 + lane];
        }

        unsigned long long p0 = pack2(a4.x, a4.y), p1 = pack2(a4.z, a4.w);
        unsigned long long q0 = pack2(b4.x, b4.y), q1 = pack2(b4.z, b4.w);
#pragma unroll
        for (int kk = 0; kk < 16; kk++) {
            float fa = __shfl_sync(0xffffffffu, eav, kk);
            float fb = __shfl_sync(0xffffffffu, eav, kk + 16);
            unsigned long long aa = pack2(fa, fa);
            unsigned long long bb = pack2(fb, fb);
            ffma2(p0, aa, w[kk].x);
            ffma2(p1, aa, w[kk].y);
            ffma2(q0, bb, w[kk].x);
            ffma2(q1, bb, w[kk].y);
        }
        float r0, r1, r2, r3;
        unpack2(p0, r0, r1); unpack2(p1, r2, r3);
        s0 += fmaxf(r0, 0.f); s1 += fmaxf(r1, 0.f);
        s2 += fmaxf(r2, 0.f); s3 += fmaxf(r3, 0.f);
        if (fmask & (1u << (2 * p))) {
            int d = __shfl_sync(0xffffffffu, dsts, 2 * p);
            float* ptr = &summed[(size_t)d * 128 + lane * 4];
            asm volatile("red.global.add.v4.f32 [%0], {%1,%2,%3,%4};"
                         :: "l"(ptr), "f"(s0), "f"(s1), "f"(s2), "f"(s3) : "memory");
            s0 = s1 = s2 = s3 = 0.f;
        }
        unpack2(q0, r0, r1); unpack2(q1, r2, r3);
        s0 += fmaxf(r0, 0.f); s1 += fmaxf(r1, 0.f);
        s2 += fmaxf(r2, 0.f); s3 += fmaxf(r3, 0.f);
        if (fmask & (1u << (2 * p + 1))) {
            int d = __shfl_sync(0xffffffffu, dsts, 2 * p + 1);
            float* ptr = &summed[(size_t)d * 128 + lane * 4];
            asm volatile("red.global.add.v4.f32 [%0], {%1,%2,%3,%4};"
                         :: "l"(ptr), "f"(s0), "f"(s1), "f"(s2), "f"(s3) : "memory");
            s0 = s1 = s2 = s3 = 0.f;
        }

        eav = eav_n; a4 = a4n; b4 = b4n;
    }
}

// ---------------- launch -------------------------------------------------------
extern "C" void kernel_launch(void* const* d_in, const int* in_sizes, int n_in,
                              void* d_out, int out_size)
{
    const float* x         = (const float*)d_in[0];
    const void*  edge_idx  = d_in[1];
    const float* edge_attr = (const float*)d_in[2];
    const float* w_msg1    = (const float*)d_in[3];
    const float* b_msg1    = (const float*)d_in[4];
    const float* w_upd1    = (const float*)d_in[5];
    const float* b_upd1    = (const float*)d_in[6];
    const float* bias1     = (const float*)d_in[7];
    const float* w_msg2    = (const float*)d_in[8];
    const float* b_msg2    = (const float*)d_in[9];
    const float* w_upd2    = (const float*)d_in[10];
    const float* b_upd2    = (const float*)d_in[11];
    const float* bias2     = (const float*)d_in[12];
    float* out = (float*)d_out;

    float *np, *sm, *h, *inv;
    cudaGetSymbolAddress((void**)&np,  g_nodeproj);
    cudaGetSymbolAddress((void**)&sm,  g_summed);
    cudaGetSymbolAddress((void**)&h,   g_h);
    cudaGetSymbolAddress((void**)&inv, g_inv);

    const int GEMM_BLOCKS = (N_NODES + 127) / 128;       // 782
    const int CNT_BLOCKS  = (N_EDGES + 255) / 256;
    const int ZS_BLOCKS   = (N_NODES * (CH / 4) + 255) / 256;
    const int EM_BLOCKS   = N_EDGES / 128;               // 12500 (4 warps/block)

    init_kernel<<<NB, 256>>>((const unsigned*)edge_idx);                 // 0
    count_kernel<<<CNT_BLOCKS, 256>>>(edge_idx);                         // 1
    reduce_kernel<<<NB, 256>>>();                                        // 2
    // PROBE at index 3: 1/8-size edgemsg so ncu profiles the edge kernel with
    // full SM residency. Reads last-replay sorted arrays (valid ids; zeros on
    // very first call), scatters into g_summed which is re-zeroed before real
    // use. Output-neutral.
    edgemsg_kernel<<<EM_BLOCKS / 8, 128>>>(np, w_msg1 + 128 * 128, sm);  // 3 ← profiled
    scanp_kernel<<<1, 512>>>();                                          // 4
    expand_kernel<<<NB, 256>>>();                                        // 5
    scatter_kernel<<<CNT_BLOCKS, 256>>>(edge_idx, edge_attr);            // 6
    gemm_kernel<128, false, false><<<GEMM_BLOCKS, 256>>>(                // 7
        x, nullptr, nullptr, w_msg1, b_msg1, nullptr, np);

    // ---- layer 1 ----
    zero_summed_kernel<<<ZS_BLOCKS, 256>>>();                            // 8
    edgemsg_kernel<<<EM_BLOCKS, 128>>>(np, w_msg1 + 128 * 128, sm);      // 9
    gemm_kernel<256, true, true><<<GEMM_BLOCKS, 256>>>(                  // 10
        x, sm, inv, w_upd1, b_upd1, bias1, h);

    // ---- layer 2 ----
    gemm_kernel<128, false, false><<<GEMM_BLOCKS, 256>>>(                // 11
        h, nullptr, nullptr, w_msg2, b_msg2, nullptr, np);
    zero_summed_kernel<<<ZS_BLOCKS, 256>>>();                            // 12
    edgemsg_kernel<<<EM_BLOCKS, 128>>>(np, w_msg2 + 128 * 128, sm);      // 13
    gemm_kernel<256, true, false><<<GEMM_BLOCKS, 256>>>(                 // 14
        h, sm, inv, w_upd2, b_upd2, bias2, out);

    (void)in_sizes; (void)n_in; (void)out_size;
}

// round 16
// speedup vs baseline: 1.0673x; 1.0673x over previous
#include <cuda_runtime.h>
#include <cstdint>

#define N_NODES 100000
#define N_EDGES 1600000
#define CH      128
#define EDIM    16
#define NB      391      // ceil(N_NODES/256)
#define EM_DEPTH 4       // cp.async pipeline depth (pairs in flight)
#define EM_SLOTS 8       // smem ring slots (2x depth: kills WAR hazard)

// ---------------- scratch (static device globals: no allocation) ----------------
__device__ float g_nodeproj[(size_t)N_NODES * CH];
__device__ float g_summed [(size_t)N_NODES * CH];
__device__ float g_h      [(size_t)N_NODES * CH];
__device__ float g_inv    [N_NODES];
__device__ int   g_cnt    [N_NODES];
__device__ int   g_off    [N_NODES];
__device__ int   g_cursor [N_NODES];
__device__ int   g_part   [512];
__device__ int   g_src_sorted[N_EDGES];
__device__ int   g_dst_sorted[N_EDGES];
__device__ float g_ea_sorted[(size_t)N_EDGES * EDIM];
__device__ int   g_is64;

// ---------------- packed f32x2 helpers (sm_103a) ----------------
static __device__ __forceinline__ unsigned long long pack2(float x, float y) {
    unsigned long long r;
    asm("mov.b64 %0, {%1, %2};" : "=l"(r) : "f"(x), "f"(y));
    return r;
}
static __device__ __forceinline__ void unpack2(unsigned long long v, float &x, float &y) {
    asm("mov.b64 {%0, %1}, %2;" : "=f"(x), "=f"(y) : "l"(v));
}
static __device__ __forceinline__ void ffma2(unsigned long long &d,
                                             unsigned long long a,
                                             unsigned long long b) {
    asm("fma.rn.f32x2 %0, %1, %2, %0;" : "+l"(d) : "l"(a), "l"(b));
}
static __device__ __forceinline__ uint32_t smem_u32(const void* p) {
    uint32_t a;
    asm("{ .reg .u64 t; cvta.to.shared.u64 t, %1; cvt.u32.u64 %0, t; }" : "=r"(a) : "l"(p));
    return a;
}

// ---------------- init: zero counts + dtype sniff (int32 vs int64) -------------
__global__ void init_kernel(const unsigned* __restrict__ p) {
    int i = blockIdx.x * 256 + threadIdx.x;
    if (i < N_NODES) g_cnt[i] = 0;
    if (blockIdx.x == 0) {
        __shared__ int nz;
        if (threadIdx.x == 0) nz = 0;
        __syncthreads();
        if (p[threadIdx.x * 2 + 1] != 0u) atomicAdd(&nz, 1);
        __syncthreads();
        if (threadIdx.x == 0) g_is64 = (nz == 0) ? 1 : 0;
    }
}

static __device__ __forceinline__ int load_eidx(const void* eidx, long long i, int is64) {
    return is64 ? (int)((const long long*)eidx)[i] : ((const int*)eidx)[i];
}

__global__ void count_kernel(const void* __restrict__ eidx) {
    long long t = (long long)blockIdx.x * blockDim.x + threadIdx.x;
    if (t >= N_EDGES) return;
    int dst = load_eidx(eidx, (long long)N_EDGES + t, g_is64);
    atomicAdd(&g_cnt[dst], 1);
}

// ---------------- parallel 3-phase exclusive scan of g_cnt ----------------------
__global__ __launch_bounds__(256) void reduce_kernel() {
    int i = blockIdx.x * 256 + threadIdx.x;
    int x = (i < N_NODES) ? g_cnt[i] : 0;
    __shared__ int ws[8];
    int lane = threadIdx.x & 31, wid = threadIdx.x >> 5;
#pragma unroll
    for (int o = 16; o; o >>= 1) x += __shfl_down_sync(0xffffffffu, x, o);
    if (lane == 0) ws[wid] = x;
    __syncthreads();
    if (wid == 0) {
        int v = (lane < 8) ? ws[lane] : 0;
#pragma unroll
        for (int o = 4; o; o >>= 1) v += __shfl_down_sync(0xffffffffu, v, o);
        if (lane == 0) g_part[blockIdx.x] = v;
    }
}

__global__ __launch_bounds__(512) void scanp_kernel() {
    int tid = threadIdx.x, lane = tid & 31, wid = tid >> 5;
    int v = (tid < NB) ? g_part[tid] : 0;
    int x = v;
#pragma unroll
    for (int o = 1; o < 32; o <<= 1) {
        int y = __shfl_up_sync(0xffffffffu, x, o);
        if (lane >= o) x += y;
    }
    __shared__ int ws[16];
    if (lane == 31) ws[wid] = x;
    __syncthreads();
    if (wid == 0) {
        int t = (lane < 16) ? ws[lane] : 0;
#pragma unroll
        for (int o = 1; o < 16; o <<= 1) {
            int y = __shfl_up_sync(0xffffffffu, t, o);
            if (lane >= o) t += y;
        }
        if (lane < 16) ws[lane] = t;
    }
    __syncthreads();
    int pre = wid ? ws[wid - 1] : 0;
    if (tid < NB) g_part[tid] = pre + x - v;   // exclusive
}

__global__ __launch_bounds__(256) void expand_kernel() {
    int i = blockIdx.x * 256 + threadIdx.x;
    int v = (i < N_NODES) ? g_cnt[i] : 0;
    int lane = threadIdx.x & 31, wid = threadIdx.x >> 5;
    int x = v;
#pragma unroll
    for (int o = 1; o < 32; o <<= 1) {
        int y = __shfl_up_sync(0xffffffffu, x, o);
        if (lane >= o) x += y;
    }
    __shared__ int ws[8];
    if (lane == 31) ws[wid] = x;
    __syncthreads();
    if (wid == 0) {
        int t = (lane < 8) ? ws[lane] : 0;
#pragma unroll
        for (int o = 1; o < 8; o <<= 1) {
            int y = __shfl_up_sync(0xffffffffu, t, o);
            if (lane >= o) t += y;
        }
        if (lane < 8) ws[lane] = t;
    }
    __syncthreads();
    int excl = (wid ? ws[wid - 1] : 0) + x - v + g_part[blockIdx.x];
    if (i < N_NODES) {
        g_off[i] = excl;
        g_cursor[i] = excl;
        g_inv[i] = 1.0f / (float)(v > 1 ? v : 1);
    }
}

// scatter edges into dst-sorted order (src, dst, edge_attr payload)
__global__ void scatter_kernel(const void* __restrict__ eidx,
                               const float* __restrict__ edge_attr) {
    long long t = (long long)blockIdx.x * blockDim.x + threadIdx.x;
    if (t >= N_EDGES) return;
    const int is64 = g_is64;
    int src = load_eidx(eidx, t, is64);
    int dst = load_eidx(eidx, (long long)N_EDGES + t, is64);
    int pos = atomicAdd(&g_cursor[dst], 1);
    g_src_sorted[pos] = src;
    g_dst_sorted[pos] = dst;
    const float4* s = reinterpret_cast<const float4*>(&edge_attr[t * EDIM]);
    float4* d = reinterpret_cast<float4*>(&g_ea_sorted[(size_t)pos * EDIM]);
    d[0] = s[0]; d[1] = s[1]; d[2] = s[2]; d[3] = s[3];
}

__global__ void zero_summed_kernel() {
    size_t i = (size_t)blockIdx.x * 256 + threadIdx.x;
    if (i < (size_t)N_NODES * (CH / 4))
        reinterpret_cast<float4*>(g_summed)[i] = make_float4(0.f, 0.f, 0.f, 0.f);
}

// ---------------- double-buffered tiled GEMM (R9-proven: 256thr, 8x8) -----------
// C[N,128] = [A0 | A1*inv[row]] @ B[KTOT,128] (+epilogue). BM=BN=128, BK=16.
template<int KTOT>
static __device__ __forceinline__ float4 loadA_elem(const float* __restrict__ A0,
                                                    const float* __restrict__ A1,
                                                    const float* __restrict__ inv,
                                                    int grow, int kb, int k4) {
    float4 v = make_float4(0.f, 0.f, 0.f, 0.f);
    if (grow < N_NODES) {
        if (KTOT == 128 || kb < 128) {
            v = *reinterpret_cast<const float4*>(&A0[(size_t)grow * 128 + kb + k4]);
        } else {
            v = *reinterpret_cast<const float4*>(&A1[(size_t)grow * 128 + (kb - 128) + k4]);
            float s = inv[grow];
            v.x *= s; v.y *= s; v.z *= s; v.w *= s;
        }
    }
    return v;
}

static __device__ __forceinline__ void stsA(float* As, int m, int k4, float4 v) {
    As[(k4 + 0) * 128 + m] = v.x;
    As[(k4 + 1) * 128 + m] = v.y;
    As[(k4 + 2) * 128 + m] = v.z;
    As[(k4 + 3) * 128 + m] = v.w;
}

static __device__ __forceinline__ void gemm_compute(const float* __restrict__ As,
                                                    const float* __restrict__ Bs,
                                                    unsigned long long acc[8][4],
                                                    int tx, int ty) {
#pragma unroll
    for (int k = 0; k < 16; k++) {
        float4 a0 = *reinterpret_cast<const float4*>(&As[k * 128 + ty * 8]);
        float4 a1 = *reinterpret_cast<const float4*>(&As[k * 128 + ty * 8 + 4]);
        ulonglong2 bb0 = *reinterpret_cast<const ulonglong2*>(&Bs[k * 128 + tx * 8]);
        ulonglong2 bb1 = *reinterpret_cast<const ulonglong2*>(&Bs[k * 128 + tx * 8 + 4]);
        float av[8] = {a0.x, a0.y, a0.z, a0.w, a1.x, a1.y, a1.z, a1.w};
        unsigned long long bv[4] = {bb0.x, bb0.y, bb1.x, bb1.y};
#pragma unroll
        for (int i = 0; i < 8; i++) {
            unsigned long long a2 = pack2(av[i], av[i]);
#pragma unroll
            for (int j = 0; j < 4; j++) ffma2(acc[i][j], a2, bv[j]);
        }
    }
}

template<int KTOT, bool NORM, bool RELU>
__global__ __launch_bounds__(256)
void gemm_kernel(const float* __restrict__ A0, const float* __restrict__ A1,
                 const float* __restrict__ inv,
                 const float* __restrict__ B,
                 const float* __restrict__ bias1, const float* __restrict__ bias2,
                 float* __restrict__ out)
{
    __shared__ float As[2][16 * 128];
    __shared__ float Bs[2][16 * 128];
    const int tid = threadIdx.x;
    const int tx = tid & 15, ty = tid >> 4;
    const int row0 = blockIdx.x * 128;
    const int mA = tid >> 2, k4 = (tid & 3) << 2;
    const int kB = tid >> 5, n4 = tid & 31;

    unsigned long long acc[8][4];
#pragma unroll
    for (int i = 0; i < 8; i++)
#pragma unroll
        for (int j = 0; j < 4; j++) acc[i][j] = 0ull;

    float4 ra0 = loadA_elem<KTOT>(A0, A1, inv, row0 + mA, 0, k4);
    float4 ra1 = loadA_elem<KTOT>(A0, A1, inv, row0 + mA + 64, 0, k4);
    float4 rb0 = reinterpret_cast<const float4*>(&B[(size_t)kB * 128])[n4];
    float4 rb1 = reinterpret_cast<const float4*>(&B[(size_t)(kB + 8) * 128])[n4];
    stsA(As[0], mA, k4, ra0);
    stsA(As[0], mA + 64, k4, ra1);
    reinterpret_cast<float4*>(&Bs[0][kB * 128])[n4] = rb0;
    reinterpret_cast<float4*>(&Bs[0][(kB + 8) * 128])[n4] = rb1;
    __syncthreads();

    int buf = 0;
    for (int kb = 16; kb < KTOT; kb += 16) {
        ra0 = loadA_elem<KTOT>(A0, A1, inv, row0 + mA, kb, k4);
        ra1 = loadA_elem<KTOT>(A0, A1, inv, row0 + mA + 64, kb, k4);
        rb0 = reinterpret_cast<const float4*>(&B[(size_t)(kb + kB) * 128])[n4];
        rb1 = reinterpret_cast<const float4*>(&B[(size_t)(kb + kB + 8) * 128])[n4];
        gemm_compute(As[buf], Bs[buf], acc, tx, ty);
        stsA(As[buf ^ 1], mA, k4, ra0);
        stsA(As[buf ^ 1], mA + 64, k4, ra1);
        reinterpret_cast<float4*>(&Bs[buf ^ 1][kB * 128])[n4] = rb0;
        reinterpret_cast<float4*>(&Bs[buf ^ 1][(kB + 8) * 128])[n4] = rb1;
        __syncthreads();
        buf ^= 1;
    }
    gemm_compute(As[buf], Bs[buf], acc, tx, ty);

    // epilogue
    float vals[8][8];
#pragma unroll
    for (int i = 0; i < 8; i++)
#pragma unroll
        for (int j = 0; j < 4; j++)
            unpack2(acc[i][j], vals[i][2 * j], vals[i][2 * j + 1]);

#pragma unroll
    for (int j = 0; j < 8; j++) {
        float b = bias1[tx * 8 + j];
#pragma unroll
        for (int i = 0; i < 8; i++) vals[i][j] += b;
    }

    float rn[8];
    if (NORM) {
        __syncthreads();
        float* ss = As[0];
        if (tid < 128) ss[tid] = 0.f;
        __syncthreads();
#pragma unroll
        for (int i = 0; i < 8; i++) {
            float p = 0.f;
#pragma unroll
            for (int j = 0; j < 8; j++) p += vals[i][j] * vals[i][j];
            atomicAdd(&ss[ty * 8 + i], p);
        }
        __syncthreads();
        if (tid < 128) {
            float s = ss[tid];
            Bs[0][tid] = 1.0f / fmaxf(sqrtf(s), 1e-12f);
        }
        __syncthreads();
#pragma unroll
        for (int i = 0; i < 8; i++) rn[i] = Bs[0][ty * 8 + i];
    }

#pragma unroll
    for (int i = 0; i < 8; i++) {
        int grow = row0 + ty * 8 + i;
        if (grow < N_NODES) {
            float o[8];
#pragma unroll
            for (int j = 0; j < 8; j++) {
                float v = vals[i][j];
                if (NORM) v = v * rn[i] + bias2[tx * 8 + j];
                if (RELU) v = fmaxf(v, 0.f);
                o[j] = v;
            }
            float4* dst = reinterpret_cast<float4*>(&out[(size_t)grow * 128 + tx * 8]);
            dst[0] = make_float4(o[0], o[1], o[2], o[3]);
            dst[1] = make_float4(o[4], o[5], o[6], o[7]);
        }
    }
}

// ---------------- edge-parallel message kernel v5: cp.async gather pipeline -----
// 32 edges/warp, W in regs, eav shfl-broadcast, gathers prefetched depth-4 into
// an 8-slot smem ring via cp.async (no register cost for in-flight data).
// Each lane reads back only its own 16B slice -> no syncwarp needed.
__global__ __launch_bounds__(128)
void edgemsg_kernel(const float* __restrict__ nodeproj,
                    const float* __restrict__ We,   // [16][128] row-major fp32
                    float* __restrict__ summed)
{
    __shared__ float4 sbuf[4][EM_SLOTS][2][32];   // 32 KB: [warp][slot][edge][lane]

    const int lane = threadIdx.x & 31;
    const int warp = threadIdx.x >> 5;

    // lane owns output channels [4*lane, 4*lane+4)
    ulonglong2 w[16];
#pragma unroll
    for (int k = 0; k < 16; k++)
        w[k] = reinterpret_cast<const ulonglong2*>(We)[k * 32 + lane];

    const long long e0 = ((long long)blockIdx.x * 4 + warp) * 32;
    if (e0 >= N_EDGES) return;

    const int srcs = g_src_sorted[e0 + lane];
    const int dsts = g_dst_sorted[e0 + lane];
    // run-end mask: bit e set iff edge e is the last edge of its dst run in chunk
    const int nxt = __shfl_down_sync(0xffffffffu, dsts, 1);
    const unsigned fmask = __ballot_sync(0xffffffffu, lane == 31 || dsts != nxt);

    const char* npb = reinterpret_cast<const char*>(nodeproj);
    const uint32_t sb = smem_u32(&sbuf[warp][0][0][0]);

    // issue pair p's two gather rows into ring slot p % EM_SLOTS
    auto issue = [&](int p) {
        int sA = __shfl_sync(0xffffffffu, srcs, 2 * p);
        int sB = __shfl_sync(0xffffffffu, srcs, 2 * p + 1);
        const char* gA = npb + ((size_t)sA * 512 + (size_t)lane * 16);
        const char* gB = npb + ((size_t)sB * 512 + (size_t)lane * 16);
        uint32_t dA = sb + (uint32_t)((p & (EM_SLOTS - 1)) * 1024 + lane * 16);
        uint32_t dB = dA + 512;
        asm volatile("cp.async.ca.shared.global [%0], [%1], 16;" :: "r"(dA), "l"(gA));
        asm volatile("cp.async.ca.shared.global [%0], [%1], 16;" :: "r"(dB), "l"(gB));
    };

    // prologue: EM_DEPTH stages in flight
#pragma unroll
    for (int s = 0; s < EM_DEPTH; s++) {
        issue(s);
        asm volatile("cp.async.commit_group;");
    }
    float eav = g_ea_sorted[e0 * EDIM + lane];   // pair 0's 2x16 attrs (128B)

    float s0 = 0.f, s1 = 0.f, s2 = 0.f, s3 = 0.f;

#pragma unroll 1
    for (int p = 0; p < 16; p++) {
        asm volatile("cp.async.wait_group %0;" :: "n"(EM_DEPTH - 1));
        float4 a4 = sbuf[warp][p & (EM_SLOTS - 1)][0][lane];
        float4 b4 = sbuf[warp][p & (EM_SLOTS - 1)][1][lane];

        // keep the pipeline full + prefetch next eav
        float eav_n = 0.f;
        if (p < 15) eav_n = g_ea_sorted[(e0 + 2 * p + 2) * EDIM + lane];
        if (p + EM_DEPTH < 16) issue(p + EM_DEPTH);
        asm volatile("cp.async.commit_group;");   // empty groups keep counting uniform

        unsigned long long p0 = pack2(a4.x, a4.y), p1 = pack2(a4.z, a4.w);
        unsigned long long q0 = pack2(b4.x, b4.y), q1 = pack2(b4.z, b4.w);
#pragma unroll
        for (int kk = 0; kk < 16; kk++) {
            float fa = __shfl_sync(0xffffffffu, eav, kk);
            float fb = __shfl_sync(0xffffffffu, eav, kk + 16);
            unsigned long long aa = pack2(fa, fa);
            unsigned long long bb = pack2(fb, fb);
            ffma2(p0, aa, w[kk].x);
            ffma2(p1, aa, w[kk].y);
            ffma2(q0, bb, w[kk].x);
            ffma2(q1, bb, w[kk].y);
        }
        float r0, r1, r2, r3;
        unpack2(p0, r0, r1); unpack2(p1, r2, r3);
        s0 += fmaxf(r0, 0.f); s1 += fmaxf(r1, 0.f);
        s2 += fmaxf(r2, 0.f); s3 += fmaxf(r3, 0.f);
        if (fmask & (1u << (2 * p))) {
            int d = __shfl_sync(0xffffffffu, dsts, 2 * p);
            float* ptr = &summed[(size_t)d * 128 + lane * 4];
            asm volatile("red.global.add.v4.f32 [%0], {%1,%2,%3,%4};"
                         :: "l"(ptr), "f"(s0), "f"(s1), "f"(s2), "f"(s3) : "memory");
            s0 = s1 = s2 = s3 = 0.f;
        }
        unpack2(q0, r0, r1); unpack2(q1, r2, r3);
        s0 += fmaxf(r0, 0.f); s1 += fmaxf(r1, 0.f);
        s2 += fmaxf(r2, 0.f); s3 += fmaxf(r3, 0.f);
        if (fmask & (1u << (2 * p + 1))) {
            int d = __shfl_sync(0xffffffffu, dsts, 2 * p + 1);
            float* ptr = &summed[(size_t)d * 128 + lane * 4];
            asm volatile("red.global.add.v4.f32 [%0], {%1,%2,%3,%4};"
                         :: "l"(ptr), "f"(s0), "f"(s1), "f"(s2), "f"(s3) : "memory");
            s0 = s1 = s2 = s3 = 0.f;
        }

        eav = eav_n;
    }
}

// ---------------- launch -------------------------------------------------------
extern "C" void kernel_launch(void* const* d_in, const int* in_sizes, int n_in,
                              void* d_out, int out_size)
{
    const float* x         = (const float*)d_in[0];
    const void*  edge_idx  = d_in[1];
    const float* edge_attr = (const float*)d_in[2];
    const float* w_msg1    = (const float*)d_in[3];
    const float* b_msg1    = (const float*)d_in[4];
    const float* w_upd1    = (const float*)d_in[5];
    const float* b_upd1    = (const float*)d_in[6];
    const float* bias1     = (const float*)d_in[7];
    const float* w_msg2    = (const float*)d_in[8];
    const float* b_msg2    = (const float*)d_in[9];
    const float* w_upd2    = (const float*)d_in[10];
    const float* b_upd2    = (const float*)d_in[11];
    const float* bias2     = (const float*)d_in[12];
    float* out = (float*)d_out;

    float *np, *sm, *h, *inv;
    cudaGetSymbolAddress((void**)&np,  g_nodeproj);
    cudaGetSymbolAddress((void**)&sm,  g_summed);
    cudaGetSymbolAddress((void**)&h,   g_h);
    cudaGetSymbolAddress((void**)&inv, g_inv);

    const int GEMM_BLOCKS = (N_NODES + 127) / 128;       // 782
    const int CNT_BLOCKS  = (N_EDGES + 255) / 256;
    const int ZS_BLOCKS   = (N_NODES * (CH / 4) + 255) / 256;
    const int EM_BLOCKS   = N_EDGES / 128;               // 12500 (4 warps/block)

    init_kernel<<<NB, 256>>>((const unsigned*)edge_idx);                 // 0
    count_kernel<<<CNT_BLOCKS, 256>>>(edge_idx);                         // 1
    reduce_kernel<<<NB, 256>>>();                                        // 2
    // PROBE at index 3: 1/8-size edgemsg so ncu profiles the edge kernel.
    // Reads last-replay sorted arrays (valid ids; zeros on very first call),
    // scatters into g_summed which is re-zeroed before real use. Output-neutral.
    edgemsg_kernel<<<EM_BLOCKS / 8, 128>>>(np, w_msg1 + 128 * 128, sm);  // 3 ← profiled
    scanp_kernel<<<1, 512>>>();                                          // 4
    expand_kernel<<<NB, 256>>>();                                        // 5
    scatter_kernel<<<CNT_BLOCKS, 256>>>(edge_idx, edge_attr);            // 6
    gemm_kernel<128, false, false><<<GEMM_BLOCKS, 256>>>(                // 7
        x, nullptr, nullptr, w_msg1, b_msg1, nullptr, np);

    // ---- layer 1 ----
    zero_summed_kernel<<<ZS_BLOCKS, 256>>>();                            // 8
    edgemsg_kernel<<<EM_BLOCKS, 128>>>(np, w_msg1 + 128 * 128, sm);      // 9
    gemm_kernel<256, true, true><<<GEMM_BLOCKS, 256>>>(                  // 10
        x, sm, inv, w_upd1, b_upd1, bias1, h);

    // ---- layer 2 ----
    gemm_kernel<128, false, false><<<GEMM_BLOCKS, 256>>>(                // 11
        h, nullptr, nullptr, w_msg2, b_msg2, nullptr, np);
    zero_summed_kernel<<<ZS_BLOCKS, 256>>>();                            // 12
    edgemsg_kernel<<<EM_BLOCKS, 128>>>(np, w_msg2 + 128 * 128, sm);      // 13
    gemm_kernel<256, true, false><<<GEMM_BLOCKS, 256>>>(                 // 14
        h, sm, inv, w_upd2, b_upd2, bias2, out);

    (void)in_sizes; (void)n_in; (void)out_size;
}

// round 17
// speedup vs baseline: 1.0820x; 1.0137x over previous
#include <cuda_runtime.h>
#include <cstdint>

#define N_NODES 100000
#define N_EDGES 1600000
#define CH      128
#define EDIM    16
#define NB      391      // ceil(N_NODES/256)

// ---------------- scratch (static device globals: no allocation) ----------------
__device__ float g_nodeproj[(size_t)N_NODES * CH];
__device__ float g_summed [(size_t)N_NODES * CH];
__device__ float g_h      [(size_t)N_NODES * CH];
__device__ float g_inv    [N_NODES];
__device__ int   g_cnt    [N_NODES];
__device__ int   g_off    [N_NODES];
__device__ int   g_cursor [N_NODES];
__device__ int   g_part   [512];
__device__ int   g_src_sorted[N_EDGES];
__device__ int   g_dst_sorted[N_EDGES];
__device__ float g_ea_sorted[(size_t)N_EDGES * EDIM];
__device__ int   g_is64;

// ---------------- packed f32x2 helpers (sm_103a) ----------------
static __device__ __forceinline__ unsigned long long pack2(float x, float y) {
    unsigned long long r;
    asm("mov.b64 %0, {%1, %2};" : "=l"(r) : "f"(x), "f"(y));
    return r;
}
static __device__ __forceinline__ void unpack2(unsigned long long v, float &x, float &y) {
    asm("mov.b64 {%0, %1}, %2;" : "=f"(x), "=f"(y) : "l"(v));
}
static __device__ __forceinline__ void ffma2(unsigned long long &d,
                                             unsigned long long a,
                                             unsigned long long b) {
    asm("fma.rn.f32x2 %0, %1, %2, %0;" : "+l"(d) : "l"(a), "l"(b));
}

// ---------------- init: zero counts + dtype sniff (int32 vs int64) -------------
__global__ void init_kernel(const unsigned* __restrict__ p) {
    int i = blockIdx.x * 256 + threadIdx.x;
    if (i < N_NODES) g_cnt[i] = 0;
    if (blockIdx.x == 0) {
        __shared__ int nz;
        if (threadIdx.x == 0) nz = 0;
        __syncthreads();
        if (p[threadIdx.x * 2 + 1] != 0u) atomicAdd(&nz, 1);
        __syncthreads();
        if (threadIdx.x == 0) g_is64 = (nz == 0) ? 1 : 0;
    }
}

static __device__ __forceinline__ int load_eidx(const void* eidx, long long i, int is64) {
    return is64 ? (int)((const long long*)eidx)[i] : ((const int*)eidx)[i];
}

__global__ void count_kernel(const void* __restrict__ eidx) {
    long long t = (long long)blockIdx.x * blockDim.x + threadIdx.x;
    if (t >= N_EDGES) return;
    int dst = load_eidx(eidx, (long long)N_EDGES + t, g_is64);
    atomicAdd(&g_cnt[dst], 1);
}

// ---------------- parallel 3-phase exclusive scan of g_cnt ----------------------
__global__ __launch_bounds__(256) void reduce_kernel() {
    int i = blockIdx.x * 256 + threadIdx.x;
    int x = (i < N_NODES) ? g_cnt[i] : 0;
    __shared__ int ws[8];
    int lane = threadIdx.x & 31, wid = threadIdx.x >> 5;
#pragma unroll
    for (int o = 16; o; o >>= 1) x += __shfl_down_sync(0xffffffffu, x, o);
    if (lane == 0) ws[wid] = x;
    __syncthreads();
    if (wid == 0) {
        int v = (lane < 8) ? ws[lane] : 0;
#pragma unroll
        for (int o = 4; o; o >>= 1) v += __shfl_down_sync(0xffffffffu, v, o);
        if (lane == 0) g_part[blockIdx.x] = v;
    }
}

__global__ __launch_bounds__(512) void scanp_kernel() {
    int tid = threadIdx.x, lane = tid & 31, wid = tid >> 5;
    int v = (tid < NB) ? g_part[tid] : 0;
    int x = v;
#pragma unroll
    for (int o = 1; o < 32; o <<= 1) {
        int y = __shfl_up_sync(0xffffffffu, x, o);
        if (lane >= o) x += y;
    }
    __shared__ int ws[16];
    if (lane == 31) ws[wid] = x;
    __syncthreads();
    if (wid == 0) {
        int t = (lane < 16) ? ws[lane] : 0;
#pragma unroll
        for (int o = 1; o < 16; o <<= 1) {
            int y = __shfl_up_sync(0xffffffffu, t, o);
            if (lane >= o) t += y;
        }
        if (lane < 16) ws[lane] = t;
    }
    __syncthreads();
    int pre = wid ? ws[wid - 1] : 0;
    if (tid < NB) g_part[tid] = pre + x - v;   // exclusive
}

__global__ __launch_bounds__(256) void expand_kernel() {
    int i = blockIdx.x * 256 + threadIdx.x;
    int v = (i < N_NODES) ? g_cnt[i] : 0;
    int lane = threadIdx.x & 31, wid = threadIdx.x >> 5;
    int x = v;
#pragma unroll
    for (int o = 1; o < 32; o <<= 1) {
        int y = __shfl_up_sync(0xffffffffu, x, o);
        if (lane >= o) x += y;
    }
    __shared__ int ws[8];
    if (lane == 31) ws[wid] = x;
    __syncthreads();
    if (wid == 0) {
        int t = (lane < 8) ? ws[lane] : 0;
#pragma unroll
        for (int o = 1; o < 8; o <<= 1) {
            int y = __shfl_up_sync(0xffffffffu, t, o);
            if (lane >= o) t += y;
        }
        if (lane < 8) ws[lane] = t;
    }
    __syncthreads();
    int excl = (wid ? ws[wid - 1] : 0) + x - v + g_part[blockIdx.x];
    if (i < N_NODES) {
        g_off[i] = excl;
        g_cursor[i] = excl;
        g_inv[i] = 1.0f / (float)(v > 1 ? v : 1);
    }
}

// scatter edges into dst-sorted order (src, dst, edge_attr payload)
__global__ void scatter_kernel(const void* __restrict__ eidx,
                               const float* __restrict__ edge_attr) {
    long long t = (long long)blockIdx.x * blockDim.x + threadIdx.x;
    if (t >= N_EDGES) return;
    const int is64 = g_is64;
    int src = load_eidx(eidx, t, is64);
    int dst = load_eidx(eidx, (long long)N_EDGES + t, is64);
    int pos = atomicAdd(&g_cursor[dst], 1);
    g_src_sorted[pos] = src;
    g_dst_sorted[pos] = dst;
    const float4* s = reinterpret_cast<const float4*>(&edge_attr[t * EDIM]);
    float4* d = reinterpret_cast<float4*>(&g_ea_sorted[(size_t)pos * EDIM]);
    d[0] = s[0]; d[1] = s[1]; d[2] = s[2]; d[3] = s[3];
}

__global__ void zero_summed_kernel() {
    size_t i = (size_t)blockIdx.x * 256 + threadIdx.x;
    if (i < (size_t)N_NODES * (CH / 4))
        reinterpret_cast<float4*>(g_summed)[i] = make_float4(0.f, 0.f, 0.f, 0.f);
}

// ---------------- double-buffered tiled GEMM (R9-proven: 256thr, 8x8) -----------
// C[N,128] = [A0 | A1*inv[row]] @ B[KTOT,128] (+epilogue). BM=BN=128, BK=16.
template<int KTOT>
static __device__ __forceinline__ float4 loadA_elem(const float* __restrict__ A0,
                                                    const float* __restrict__ A1,
                                                    const float* __restrict__ inv,
                                                    int grow, int kb, int k4) {
    float4 v = make_float4(0.f, 0.f, 0.f, 0.f);
    if (grow < N_NODES) {
        if (KTOT == 128 || kb < 128) {
            v = *reinterpret_cast<const float4*>(&A0[(size_t)grow * 128 + kb + k4]);
        } else {
            v = *reinterpret_cast<const float4*>(&A1[(size_t)grow * 128 + (kb - 128) + k4]);
            float s = inv[grow];
            v.x *= s; v.y *= s; v.z *= s; v.w *= s;
        }
    }
    return v;
}

static __device__ __forceinline__ void stsA(float* As, int m, int k4, float4 v) {
    As[(k4 + 0) * 128 + m] = v.x;
    As[(k4 + 1) * 128 + m] = v.y;
    As[(k4 + 2) * 128 + m] = v.z;
    As[(k4 + 3) * 128 + m] = v.w;
}

static __device__ __forceinline__ void gemm_compute(const float* __restrict__ As,
                                                    const float* __restrict__ Bs,
                                                    unsigned long long acc[8][4],
                                                    int tx, int ty) {
#pragma unroll
    for (int k = 0; k < 16; k++) {
        float4 a0 = *reinterpret_cast<const float4*>(&As[k * 128 + ty * 8]);
        float4 a1 = *reinterpret_cast<const float4*>(&As[k * 128 + ty * 8 + 4]);
        ulonglong2 bb0 = *reinterpret_cast<const ulonglong2*>(&Bs[k * 128 + tx * 8]);
        ulonglong2 bb1 = *reinterpret_cast<const ulonglong2*>(&Bs[k * 128 + tx * 8 + 4]);
        float av[8] = {a0.x, a0.y, a0.z, a0.w, a1.x, a1.y, a1.z, a1.w};
        unsigned long long bv[4] = {bb0.x, bb0.y, bb1.x, bb1.y};
#pragma unroll
        for (int i = 0; i < 8; i++) {
            unsigned long long a2 = pack2(av[i], av[i]);
#pragma unroll
            for (int j = 0; j < 4; j++) ffma2(acc[i][j], a2, bv[j]);
        }
    }
}

template<int KTOT, bool NORM, bool RELU>
__global__ __launch_bounds__(256)
void gemm_kernel(const float* __restrict__ A0, const float* __restrict__ A1,
                 const float* __restrict__ inv,
                 const float* __restrict__ B,
                 const float* __restrict__ bias1, const float* __restrict__ bias2,
                 float* __restrict__ out)
{
    __shared__ float As[2][16 * 128];
    __shared__ float Bs[2][16 * 128];
    const int tid = threadIdx.x;
    const int tx = tid & 15, ty = tid >> 4;
    const int row0 = blockIdx.x * 128;
    const int mA = tid >> 2, k4 = (tid & 3) << 2;
    const int kB = tid >> 5, n4 = tid & 31;

    unsigned long long acc[8][4];
#pragma unroll
    for (int i = 0; i < 8; i++)
#pragma unroll
        for (int j = 0; j < 4; j++) acc[i][j] = 0ull;

    float4 ra0 = loadA_elem<KTOT>(A0, A1, inv, row0 + mA, 0, k4);
    float4 ra1 = loadA_elem<KTOT>(A0, A1, inv, row0 + mA + 64, 0, k4);
    float4 rb0 = reinterpret_cast<const float4*>(&B[(size_t)kB * 128])[n4];
    float4 rb1 = reinterpret_cast<const float4*>(&B[(size_t)(kB + 8) * 128])[n4];
    stsA(As[0], mA, k4, ra0);
    stsA(As[0], mA + 64, k4, ra1);
    reinterpret_cast<float4*>(&Bs[0][kB * 128])[n4] = rb0;
    reinterpret_cast<float4*>(&Bs[0][(kB + 8) * 128])[n4] = rb1;
    __syncthreads();

    int buf = 0;
    for (int kb = 16; kb < KTOT; kb += 16) {
        ra0 = loadA_elem<KTOT>(A0, A1, inv, row0 + mA, kb, k4);
        ra1 = loadA_elem<KTOT>(A0, A1, inv, row0 + mA + 64, kb, k4);
        rb0 = reinterpret_cast<const float4*>(&B[(size_t)(kb + kB) * 128])[n4];
        rb1 = reinterpret_cast<const float4*>(&B[(size_t)(kb + kB + 8) * 128])[n4];
        gemm_compute(As[buf], Bs[buf], acc, tx, ty);
        stsA(As[buf ^ 1], mA, k4, ra0);
        stsA(As[buf ^ 1], mA + 64, k4, ra1);
        reinterpret_cast<float4*>(&Bs[buf ^ 1][kB * 128])[n4] = rb0;
        reinterpret_cast<float4*>(&Bs[buf ^ 1][(kB + 8) * 128])[n4] = rb1;
        __syncthreads();
        buf ^= 1;
    }
    gemm_compute(As[buf], Bs[buf], acc, tx, ty);

    // epilogue
    float vals[8][8];
#pragma unroll
    for (int i = 0; i < 8; i++)
#pragma unroll
        for (int j = 0; j < 4; j++)
            unpack2(acc[i][j], vals[i][2 * j], vals[i][2 * j + 1]);

#pragma unroll
    for (int j = 0; j < 8; j++) {
        float b = bias1[tx * 8 + j];
#pragma unroll
        for (int i = 0; i < 8; i++) vals[i][j] += b;
    }

    float rn[8];
    if (NORM) {
        __syncthreads();
        float* ss = As[0];
        if (tid < 128) ss[tid] = 0.f;
        __syncthreads();
#pragma unroll
        for (int i = 0; i < 8; i++) {
            float p = 0.f;
#pragma unroll
            for (int j = 0; j < 8; j++) p += vals[i][j] * vals[i][j];
            atomicAdd(&ss[ty * 8 + i], p);
        }
        __syncthreads();
        if (tid < 128) {
            float s = ss[tid];
            Bs[0][tid] = 1.0f / fmaxf(sqrtf(s), 1e-12f);
        }
        __syncthreads();
#pragma unroll
        for (int i = 0; i < 8; i++) rn[i] = Bs[0][ty * 8 + i];
    }

#pragma unroll
    for (int i = 0; i < 8; i++) {
        int grow = row0 + ty * 8 + i;
        if (grow < N_NODES) {
            float o[8];
#pragma unroll
            for (int j = 0; j < 8; j++) {
                float v = vals[i][j];
                if (NORM) v = v * rn[i] + bias2[tx * 8 + j];
                if (RELU) v = fmaxf(v, 0.f);
                o[j] = v;
            }
            float4* dst = reinterpret_cast<float4*>(&out[(size_t)grow * 128 + tx * 8]);
            dst[0] = make_float4(o[0], o[1], o[2], o[3]);
            dst[1] = make_float4(o[4], o[5], o[6], o[7]);
        }
    }
}

// ---------------- edge-parallel message kernel (R9 structure, 6 CTAs/SM) --------
// summed[dst] += relu(nodeproj[src] + ea @ We); runs of equal dst flushed with
// one red.global.add.v4 per lane. N_EDGES == 32 * 50000 exactly.
// __launch_bounds__(128, 6): cap regs ~85 so 6 CTAs (24 warps) fit per SM.
__global__ __launch_bounds__(128, 6)
void edgemsg_kernel(const float* __restrict__ nodeproj,
                    const float* __restrict__ We,   // [16][128] row-major fp32
                    float* __restrict__ summed)
{
    const int lane = threadIdx.x & 31;
    const int warp = threadIdx.x >> 5;

    // lane owns output channels [4*lane, 4*lane+4)
    ulonglong2 w[16];
#pragma unroll
    for (int k = 0; k < 16; k++)
        w[k] = reinterpret_cast<const ulonglong2*>(We)[k * 32 + lane];

    const long long e0 = ((long long)blockIdx.x * 4 + warp) * 32;
    if (e0 >= N_EDGES) return;
    const float4* np4 = reinterpret_cast<const float4*>(nodeproj);

    const int srcs = g_src_sorted[e0 + lane];
    const int dsts = g_dst_sorted[e0 + lane];

    int i = 0;
    while (i < 32) {
        const int dst = __shfl_sync(0xffffffffu, dsts, i);
        unsigned neq = __ballot_sync(0xffffffffu, dsts != dst) & (0xffffffffu << i);
        const int j = neq ? (__ffs(neq) - 1) : 32;   // run = [i, j)

        float s0 = 0.f, s1 = 0.f, s2 = 0.f, s3 = 0.f;

        int k = i;
        for (; k + 2 <= j; k += 2) {
            const long long e = e0 + k;
            const int src0 = __shfl_sync(0xffffffffu, srcs, k);
            const int src1 = __shfl_sync(0xffffffffu, srcs, k + 1);
            float eav = g_ea_sorted[e * EDIM + lane];   // 2 edges x 16 attrs, 128B

            float4 a4 = np4[(size_t)src0 * 32 + lane];
            float4 b4 = np4[(size_t)src1 * 32 + lane];
            unsigned long long p0 = pack2(a4.x, a4.y), p1 = pack2(a4.z, a4.w);
            unsigned long long q0 = pack2(b4.x, b4.y), q1 = pack2(b4.z, b4.w);
#pragma unroll
            for (int kk = 0; kk < 16; kk++) {
                float fa = __shfl_sync(0xffffffffu, eav, kk);
                float fb = __shfl_sync(0xffffffffu, eav, kk + 16);
                unsigned long long aa = pack2(fa, fa);
                unsigned long long bb = pack2(fb, fb);
                ffma2(p0, aa, w[kk].x);
                ffma2(p1, aa, w[kk].y);
                ffma2(q0, bb, w[kk].x);
                ffma2(q1, bb, w[kk].y);
            }
            float r0, r1, r2, r3, t0, t1, t2, t3;
            unpack2(p0, r0, r1); unpack2(p1, r2, r3);
            unpack2(q0, t0, t1); unpack2(q1, t2, t3);
            s0 += fmaxf(r0, 0.f) + fmaxf(t0, 0.f);
            s1 += fmaxf(r1, 0.f) + fmaxf(t1, 0.f);
            s2 += fmaxf(r2, 0.f) + fmaxf(t2, 0.f);
            s3 += fmaxf(r3, 0.f) + fmaxf(t3, 0.f);
        }
        if (k < j) {
            const long long e = e0 + k;
            const int src = __shfl_sync(0xffffffffu, srcs, k);
            float eav = (lane < 16) ? g_ea_sorted[e * EDIM + lane] : 0.f;
            float4 a4 = np4[(size_t)src * 32 + lane];
            unsigned long long p0 = pack2(a4.x, a4.y), p1 = pack2(a4.z, a4.w);
#pragma unroll
            for (int kk = 0; kk < 16; kk++) {
                float fa = __shfl_sync(0xffffffffu, eav, kk);
                unsigned long long aa = pack2(fa, fa);
                ffma2(p0, aa, w[kk].x);
                ffma2(p1, aa, w[kk].y);
            }
            float r0, r1, r2, r3;
            unpack2(p0, r0, r1); unpack2(p1, r2, r3);
            s0 += fmaxf(r0, 0.f);
            s1 += fmaxf(r1, 0.f);
            s2 += fmaxf(r2, 0.f);
            s3 += fmaxf(r3, 0.f);
        }

        float* p = &summed[(size_t)dst * 128 + lane * 4];
        asm volatile("red.global.add.v4.f32 [%0], {%1,%2,%3,%4};"
                     :: "l"(p), "f"(s0), "f"(s1), "f"(s2), "f"(s3) : "memory");
        i = j;
    }
}

// ---------------- launch -------------------------------------------------------
extern "C" void kernel_launch(void* const* d_in, const int* in_sizes, int n_in,
                              void* d_out, int out_size)
{
    const float* x         = (const float*)d_in[0];
    const void*  edge_idx  = d_in[1];
    const float* edge_attr = (const float*)d_in[2];
    const float* w_msg1    = (const float*)d_in[3];
    const float* b_msg1    = (const float*)d_in[4];
    const float* w_upd1    = (const float*)d_in[5];
    const float* b_upd1    = (const float*)d_in[6];
    const float* bias1     = (const float*)d_in[7];
    const float* w_msg2    = (const float*)d_in[8];
    const float* b_msg2    = (const float*)d_in[9];
    const float* w_upd2    = (const float*)d_in[10];
    const float* b_upd2    = (const float*)d_in[11];
    const float* bias2     = (const float*)d_in[12];
    float* out = (float*)d_out;

    float *np, *sm, *h, *inv;
    cudaGetSymbolAddress((void**)&np,  g_nodeproj);
    cudaGetSymbolAddress((void**)&sm,  g_summed);
    cudaGetSymbolAddress((void**)&h,   g_h);
    cudaGetSymbolAddress((void**)&inv, g_inv);

    const int GEMM_BLOCKS = (N_NODES + 127) / 128;       // 782
    const int CNT_BLOCKS  = (N_EDGES + 255) / 256;
    const int ZS_BLOCKS   = (N_NODES * (CH / 4) + 255) / 256;
    const int EM_BLOCKS   = N_EDGES / 128;               // 12500 (4 warps/block)

    init_kernel<<<NB, 256>>>((const unsigned*)edge_idx);                 // 0
    count_kernel<<<CNT_BLOCKS, 256>>>(edge_idx);                         // 1
    reduce_kernel<<<NB, 256>>>();                                        // 2
    gemm_kernel<128, false, false><<<GEMM_BLOCKS, 256>>>(                // 3
        x, nullptr, nullptr, w_msg1, b_msg1, nullptr, np);
    scanp_kernel<<<1, 512>>>();                                          // 4
    expand_kernel<<<NB, 256>>>();                                        // 5
    scatter_kernel<<<CNT_BLOCKS, 256>>>(edge_idx, edge_attr);            // 6

    // ---- layer 1 (nodeproj computed at launch 3) ----
    zero_summed_kernel<<<ZS_BLOCKS, 256>>>();                            // 7
    edgemsg_kernel<<<EM_BLOCKS, 128>>>(np, w_msg1 + 128 * 128, sm);      // 8
    gemm_kernel<256, true, true><<<GEMM_BLOCKS, 256>>>(                  // 9
        x, sm, inv, w_upd1, b_upd1, bias1, h);

    // ---- layer 2 ----
    gemm_kernel<128, false, false><<<GEMM_BLOCKS, 256>>>(                // 10
        h, nullptr, nullptr, w_msg2, b_msg2, nullptr, np);
    zero_summed_kernel<<<ZS_BLOCKS, 256>>>();                            // 11
    edgemsg_kernel<<<EM_BLOCKS, 128>>>(np, w_msg2 + 128 * 128, sm);      // 12
    gemm_kernel<256, true, false><<<GEMM_BLOCKS, 256>>>(                 // 13
        h, sm, inv, w_upd2, b_upd2, bias2, out);

    (void)in_sizes; (void)n_in; (void)out_size;
}